// round 1
// baseline (speedup 1.0000x reference)
#include <cuda_runtime.h>
#include <cstdint>

// Problem constants
#define BB 32
#define NN 8192
#define GG 128
#define MM 8320            // N + G
#define NSORT 16384        // next pow2 >= MM
#define KOUT 512
#define MAXFG 128

// Scratch (no allocations allowed)
__device__ unsigned long long g_keys[BB * NSORT];
__device__ unsigned char g_p2l[BB * MM];

__device__ __forceinline__ unsigned int fkey(float f) {
    unsigned int u = __float_as_uint(f);
    return (u & 0x80000000u) ? ~u : (u | 0x80000000u);
}

// ---------------------------------------------------------------------------
// K1: per-box IoU max/argmax over 128 gts, band classification, key build.
// grid = BB*8 blocks of 256 threads (full-chip wave).
// ---------------------------------------------------------------------------
__global__ __launch_bounds__(256) void k_iou(
    const float4* __restrict__ boxes,   // [B][N]  (ymin,xmin,ymax,xmax)
    const float4* __restrict__ gts,     // [B][G]
    const float*  __restrict__ noise)   // [B][M]
{
    __shared__ float4 sgt[GG];
    __shared__ float  sga[GG];
    const int b     = blockIdx.x >> 3;
    const int chunk = blockIdx.x & 7;
    const int tid   = threadIdx.x;

    if (tid < GG) {
        float4 g = gts[b * GG + tid];
        sgt[tid] = g;
        sga[tid] = (g.z - g.x) * (g.w - g.y);
    }
    __syncthreads();

    const int per = MM / 8;   // 1040
    const int mstart = chunk * per;
    for (int m = mstart + tid; m < mstart + per; m += 256) {
        float4 bx = (m < NN) ? boxes[b * NN + m] : gts[b * GG + (m - NN)];
        float ba = (bx.z - bx.x) * (bx.w - bx.y);

        // g = 0 peel
        float bi, bu; int bg = 0;
        {
            float4 gt = sgt[0];
            float ih = fminf(bx.z, gt.z) - fmaxf(bx.x, gt.x);
            float iw = fminf(bx.w, gt.w) - fmaxf(bx.y, gt.y);
            bi = fmaxf(ih, 0.f) * fmaxf(iw, 0.f);
            bu = ba + sga[0] - bi;
        }
        #pragma unroll 4
        for (int g = 1; g < GG; g++) {
            float4 gt = sgt[g];
            float ih = fminf(bx.z, gt.z) - fmaxf(bx.x, gt.x);
            float iw = fminf(bx.w, gt.w) - fmaxf(bx.y, gt.y);
            float ia = fmaxf(ih, 0.f) * fmaxf(iw, 0.f);
            float un = ba + sga[g] - ia;
            // iou_g > best  <=>  ia/un > bi/bu  <=>  ia*bu > bi*un  (all >0)
            if (ia * bu > bi * un) { bi = ia; bu = un; bg = g; }
        }
        float iou = __fdividef(bi, bu);
        bool pos = iou > 0.5f;
        bool neg = iou < 0.5f;          // iou >= 0 always
        float nv = noise[b * MM + m];
        float c = pos ? (2.0f + nv) : (neg ? nv : -1.0f);
        unsigned long long key =
            ((unsigned long long)fkey(c) << 32) |
            (unsigned long long)(0xFFFFFFFFu - (unsigned)m);
        g_keys[b * NSORT + m] = key;
        g_p2l[b * MM + m] = (unsigned char)bg;
    }
}

// ---------------------------------------------------------------------------
// K2: per-batch bitonic sort (descending) of 16384 u64 keys in smem,
// then emit the 512 selected outputs.
// grid = BB blocks of 1024 threads, 128KB dynamic smem.
// ---------------------------------------------------------------------------
__global__ __launch_bounds__(1024) void k_sort_out(
    const float4* __restrict__ boxes,
    const float4* __restrict__ gts,
    const int*    __restrict__ labels,   // [B][G]
    float*        __restrict__ out)
{
    extern __shared__ unsigned long long sk[];
    const int b = blockIdx.x;
    const int tid = threadIdx.x;

    for (int i = tid; i < NSORT; i += 1024)
        sk[i] = (i < MM) ? g_keys[b * NSORT + i] : 0ULL;
    __syncthreads();

    for (unsigned k = 2; k <= NSORT; k <<= 1) {
        for (unsigned j = k >> 1; j > 0; j >>= 1) {
            for (unsigned t = tid; t < NSORT / 2; t += 1024) {
                unsigned lo = t & (j - 1);
                unsigned i  = ((t - lo) << 1) + lo;
                unsigned p  = i + j;
                unsigned long long a = sk[i], c = sk[p];
                bool desc = (i & k) == 0;
                if (desc ? (a < c) : (a > c)) { sk[i] = c; sk[p] = a; }
            }
            __syncthreads();
        }
    }

    // pos_count = #keys with band >= 2.0  (encoded hi >= 0xC0000000)
    __shared__ int s_pc;
    if (tid == 0) {
        const unsigned long long TH = 0xC000000000000000ULL;
        int lo = 0, hi = NSORT;
        while (lo < hi) {
            int mid = (lo + hi) >> 1;
            if (sk[mid] >= TH) lo = mid + 1; else hi = mid;
        }
        s_pc = lo;
    }
    __syncthreads();

    if (tid < KOUT) {
        const int pc   = s_pc;
        const int nsel = pc < MAXFG ? pc : MAXFG;
        const int j    = tid;
        const int src  = (j < nsel) ? j : (pc + (j - nsel));  // <= 8704 < NSORT
        unsigned long long key = sk[src];
        unsigned hi = (unsigned)(key >> 32);
        unsigned m  = 0xFFFFFFFFu - (unsigned)(key & 0xFFFFFFFFu);
        bool posb  = hi >= 0xC0000000u;
        bool valid = (hi >= 0x80000000u) && (m < MM);  // pos or neg band

        float4 roi = make_float4(0.f, 0.f, 0.f, 0.f);
        if (valid) roi = (m < NN) ? boxes[b * NN + m] : gts[b * GG + (m - NN)];

        float4 bt = make_float4(0.f, 0.f, 0.f, 0.f);
        int cls = 0, p2l = 0;
        if (posb && m < MM) {
            int g = (int)g_p2l[b * MM + m];
            bt  = gts[b * GG + g];
            cls = labels[b * GG + g];
            p2l = g;
        }

        // out layout (float32): sbox[32,512,4] ++ scls[32,512] ++ rois[32,512,4] ++ sp2l[32,512]
        float4* sbox_o = (float4*)out + b * KOUT + j;
        float*  scls_o = out + BB * KOUT * 4 + b * KOUT + j;
        float4* rois_o = (float4*)(out + BB * KOUT * 4 + BB * KOUT) + b * KOUT + j;
        float*  sp2l_o = out + BB * KOUT * 4 + BB * KOUT + BB * KOUT * 4 + b * KOUT + j;
        *sbox_o = bt;
        *scls_o = (float)cls;
        *rois_o = roi;
        *sp2l_o = (float)p2l;
    }
}

extern "C" void kernel_launch(void* const* d_in, const int* in_sizes, int n_in,
                              void* d_out, int out_size) {
    const float4* boxes  = (const float4*)d_in[0];
    const float4* gts    = (const float4*)d_in[1];
    const int*    labels = (const int*)d_in[2];
    const float*  noise  = (const float*)d_in[3];
    float* out = (float*)d_out;

    cudaFuncSetAttribute(k_sort_out, cudaFuncAttributeMaxDynamicSharedMemorySize,
                         NSORT * (int)sizeof(unsigned long long));

    k_iou<<<BB * 8, 256>>>(boxes, gts, noise);
    k_sort_out<<<BB, 1024, NSORT * sizeof(unsigned long long)>>>(boxes, gts, labels, out);
}

// round 2
// speedup vs baseline: 3.1142x; 3.1142x over previous
#include <cuda_runtime.h>
#include <cstdint>

// Problem constants
#define BB 32
#define NN 8192
#define GG 128
#define MM 8320            // N + G
#define KOUT 512
#define MAXFG 128
#define CCAP 2048          // compact buffer capacity (pow2, bitonic-sorted)

// Scratch (no allocations allowed)
__device__ unsigned long long g_keys[BB * MM];
__device__ unsigned char g_p2l[BB * MM];

__device__ __forceinline__ unsigned int fkey(float f) {
    unsigned int u = __float_as_uint(f);
    return (u & 0x80000000u) ? ~u : (u | 0x80000000u);
}

// Monotone 256-bin coarsening of the key's high word.
// invalid (c<0) -> -1 ; neg band c in [0,1) -> bins 0..127 ; pos band c in [2,3) -> 128..255
__device__ __forceinline__ int binof(unsigned hi) {
    if (hi < 0x80000000u) return -1;
    float c = __uint_as_float(hi ^ 0x80000000u);
    if (hi >= 0xC0000000u) {
        int t = (int)((c - 2.0f) * 128.0f);
        return 128 + (t > 127 ? 127 : t);
    }
    int t = (int)(c * 128.0f);
    return t > 127 ? 127 : t;
}

// ---------------------------------------------------------------------------
// K1: per-box IoU max/argmax over 128 gts, band classification, key build.
// ---------------------------------------------------------------------------
__global__ __launch_bounds__(256) void k_iou(
    const float4* __restrict__ boxes,   // [B][N]  (ymin,xmin,ymax,xmax)
    const float4* __restrict__ gts,     // [B][G]
    const float*  __restrict__ noise)   // [B][M]
{
    __shared__ float4 sgt[GG];
    __shared__ float  sga[GG];
    const int b     = blockIdx.x >> 3;
    const int chunk = blockIdx.x & 7;
    const int tid   = threadIdx.x;

    if (tid < GG) {
        float4 g = gts[b * GG + tid];
        sgt[tid] = g;
        sga[tid] = (g.z - g.x) * (g.w - g.y);
    }
    __syncthreads();

    const int per = MM / 8;   // 1040
    const int mstart = chunk * per;
    for (int m = mstart + tid; m < mstart + per; m += 256) {
        float4 bx = (m < NN) ? boxes[b * NN + m] : gts[b * GG + (m - NN)];
        float ba = (bx.z - bx.x) * (bx.w - bx.y);

        float bi, bu; int bg = 0;
        {
            float4 gt = sgt[0];
            float ih = fminf(bx.z, gt.z) - fmaxf(bx.x, gt.x);
            float iw = fminf(bx.w, gt.w) - fmaxf(bx.y, gt.y);
            bi = fmaxf(ih, 0.f) * fmaxf(iw, 0.f);
            bu = ba + sga[0] - bi;
        }
        #pragma unroll 4
        for (int g = 1; g < GG; g++) {
            float4 gt = sgt[g];
            float ih = fminf(bx.z, gt.z) - fmaxf(bx.x, gt.x);
            float iw = fminf(bx.w, gt.w) - fmaxf(bx.y, gt.y);
            float ia = fmaxf(ih, 0.f) * fmaxf(iw, 0.f);
            float un = ba + sga[g] - ia;
            // iou_g > best  <=>  ia*bu > bi*un  (all positive)
            if (ia * bu > bi * un) { bi = ia; bu = un; bg = g; }
        }
        float iou = __fdividef(bi, bu);
        bool pos = iou > 0.5f;
        bool neg = iou < 0.5f;
        float nv = noise[b * MM + m];
        float c = pos ? (2.0f + nv) : (neg ? nv : -1.0f);
        unsigned long long key =
            ((unsigned long long)fkey(c) << 32) |
            (unsigned long long)(0xFFFFFFFFu - (unsigned)m);
        g_keys[b * MM + m] = key;
        g_p2l[b * MM + m] = (unsigned char)bg;
    }
}

// ---------------------------------------------------------------------------
// K2: histogram radix-select -> compact (~700 items) -> bitonic sort 2048 ->
// emit 512 outputs. grid = BB blocks of 1024 threads, static smem ~17.3KB.
// ---------------------------------------------------------------------------
__global__ __launch_bounds__(1024) void k_select_out(
    const float4* __restrict__ boxes,
    const float4* __restrict__ gts,
    const int*    __restrict__ labels,
    float*        __restrict__ out)
{
    __shared__ unsigned long long buf[CCAP];
    __shared__ int hist[256];
    __shared__ int s_cnt, s_tpos, s_tneg, s_pc, s_ppc;
    const int b = blockIdx.x;
    const int tid = threadIdx.x;
    const unsigned long long* __restrict__ keys = g_keys + b * MM;

    if (tid < 256) hist[tid] = 0;
    if (tid == 0) s_cnt = 0;
    __syncthreads();

    // Pass 1: histogram
    for (int i = tid; i < MM; i += 1024) {
        int bin = binof((unsigned)(keys[i] >> 32));
        if (bin >= 0) atomicAdd(&hist[bin], 1);
    }
    __syncthreads();

    // Thresholds (serial over 256 bins — trivial)
    if (tid == 0) {
        int cum = 0, tpos = 128;
        for (int k = 255; k >= 128; k--) { cum += hist[k]; if (cum >= MAXFG) { tpos = k; break; } }
        int pc = 0;
        for (int k = 128; k < 256; k++) pc += hist[k];
        int ppc = 0;
        for (int k = tpos; k < 256; k++) ppc += hist[k];
        int cumn = 0, tneg = 0;
        for (int k = 127; k >= 0; k--) { cumn += hist[k]; if (cumn >= KOUT) { tneg = k; break; } }
        s_tpos = tpos; s_tneg = tneg; s_pc = pc; s_ppc = ppc;
    }
    __syncthreads();
    const int tpos = s_tpos, tneg = s_tneg;

    // Pass 2: compact survivors
    for (int i = tid; i < MM; i += 1024) {
        unsigned long long k = keys[i];
        int bin = binof((unsigned)(k >> 32));
        bool take = (bin >= 128) ? (bin >= tpos) : (bin >= tneg && bin >= 0);
        if (take) {
            int p = atomicAdd(&s_cnt, 1);
            if (p < CCAP) buf[p] = k;
        }
    }
    __syncthreads();
    const int cnt = s_cnt < CCAP ? s_cnt : CCAP;
    for (int i = tid; i < CCAP; i += 1024)
        if (i >= cnt) buf[i] = 0ULL;
    __syncthreads();

    // Bitonic sort 2048 descending (1024 threads, one pair each per substage)
    for (unsigned k = 2; k <= CCAP; k <<= 1) {
        for (unsigned j = k >> 1; j > 0; j >>= 1) {
            unsigned lo = tid & (j - 1);
            unsigned i  = ((tid - lo) << 1) + lo;
            unsigned p  = i + j;
            unsigned long long a = buf[i], c = buf[p];
            bool desc = (i & k) == 0;
            if (desc ? (a < c) : (a > c)) { buf[i] = c; buf[p] = a; }
            __syncthreads();
        }
    }

    // Emit outputs
    if (tid < KOUT) {
        const int pc   = s_pc;
        const int ppc  = s_ppc;                    // compacted pos count (sorted first)
        const int nsel = pc < MAXFG ? pc : MAXFG;
        const int j    = tid;
        const int src  = (j < nsel) ? j : (ppc + (j - nsel));
        unsigned long long key = (src < CCAP) ? buf[src] : 0ULL;
        unsigned hi = (unsigned)(key >> 32);
        unsigned m  = 0xFFFFFFFFu - (unsigned)(key & 0xFFFFFFFFu);
        bool posb  = hi >= 0xC0000000u;
        bool valid = (hi >= 0x80000000u) && (m < MM);

        float4 roi = make_float4(0.f, 0.f, 0.f, 0.f);
        if (valid) roi = (m < NN) ? boxes[b * NN + m] : gts[b * GG + (m - NN)];

        float4 bt = make_float4(0.f, 0.f, 0.f, 0.f);
        int cls = 0, p2l = 0;
        if (posb && m < MM) {
            int g = (int)g_p2l[b * MM + m];
            bt  = gts[b * GG + g];
            cls = labels[b * GG + g];
            p2l = g;
        }

        // out layout (float32): sbox[32,512,4] ++ scls[32,512] ++ rois[32,512,4] ++ sp2l[32,512]
        float4* sbox_o = (float4*)out + b * KOUT + j;
        float*  scls_o = out + BB * KOUT * 4 + b * KOUT + j;
        float4* rois_o = (float4*)(out + BB * KOUT * 4 + BB * KOUT) + b * KOUT + j;
        float*  sp2l_o = out + BB * KOUT * 4 + BB * KOUT + BB * KOUT * 4 + b * KOUT + j;
        *sbox_o = bt;
        *scls_o = (float)cls;
        *rois_o = roi;
        *sp2l_o = (float)p2l;
    }
}

extern "C" void kernel_launch(void* const* d_in, const int* in_sizes, int n_in,
                              void* d_out, int out_size) {
    const float4* boxes  = (const float4*)d_in[0];
    const float4* gts    = (const float4*)d_in[1];
    const int*    labels = (const int*)d_in[2];
    const float*  noise  = (const float*)d_in[3];
    float* out = (float*)d_out;

    k_iou<<<BB * 8, 256>>>(boxes, gts, noise);
    k_select_out<<<BB, 1024>>>(boxes, gts, labels, out);
}

// round 3
// speedup vs baseline: 3.6495x; 1.1719x over previous
#include <cuda_runtime.h>
#include <cstdint>

// Problem constants
#define BB 32
#define NN 8192
#define GG 128
#define MM 8320            // N + G
#define KOUT 512
#define MAXFG 128

#define NBIN_NEG 512
#define NBIN_POS 256
#define NBINS 768          // neg bins [0,512), pos bins [512,768)
#define BCAP 64            // bucket capacity (expected load ~16)

#define CHUNKS 37          // per-batch chunks in k_iou (32*37 = 1184 = 8*148 blocks)
#define CHUNK 225          // ceil(8320/37)

// Scratch (no allocations allowed). g_hist is zero at load; k_select re-zeroes
// after reading so graph replays are deterministic.
__device__ int g_hist[BB * NBINS];
__device__ unsigned long long g_bucket[BB * NBINS * BCAP];
__device__ unsigned char g_p2l[BB * MM];

__device__ __forceinline__ unsigned int fkey(float f) {
    unsigned int u = __float_as_uint(f);
    return (u & 0x80000000u) ? ~u : (u | 0x80000000u);
}

// Monotone fine binning of the key's high word.
// invalid -> -1 ; neg band c in [0,1) -> 0..511 ; pos band c in [2,3) -> 512..767
__device__ __forceinline__ int binof(unsigned hi) {
    if (hi < 0x80000000u) return -1;
    float c = __uint_as_float(hi ^ 0x80000000u);
    if (hi >= 0xC0000000u) {
        int t = (int)((c - 2.0f) * (float)NBIN_POS);     // exact: c-2 is Sterbenz-exact
        return NBIN_NEG + (t > NBIN_POS - 1 ? NBIN_POS - 1 : t);
    }
    int t = (int)(c * (float)NBIN_NEG);
    return t > NBIN_NEG - 1 ? NBIN_NEG - 1 : t;
}

// ---------------------------------------------------------------------------
// K1: IoU max/argmax over 128 gts, band classification, bucketed key scatter.
// grid = 1184 blocks x 128 threads (8 blocks/SM exactly -> balanced wave).
// ---------------------------------------------------------------------------
__global__ __launch_bounds__(128) void k_iou(
    const float4* __restrict__ boxes,   // [B][N]  (ymin,xmin,ymax,xmax)
    const float4* __restrict__ gts,     // [B][G]
    const float*  __restrict__ noise)   // [B][M]
{
    __shared__ float4 sgt[GG];
    __shared__ float  sga[GG];
    const int b     = blockIdx.x / CHUNKS;
    const int chunk = blockIdx.x % CHUNKS;
    const int tid   = threadIdx.x;

    {
        float4 g = gts[b * GG + tid];   // 128 threads, 128 gts
        sgt[tid] = g;
        sga[tid] = (g.z - g.x) * (g.w - g.y);
    }
    __syncthreads();

    const int mstart = chunk * CHUNK;
    const int mend   = (mstart + CHUNK < MM) ? (mstart + CHUNK) : MM;
    for (int m = mstart + tid; m < mend; m += 128) {
        float4 bx = (m < NN) ? boxes[b * NN + m] : gts[b * GG + (m - NN)];
        float ba = (bx.z - bx.x) * (bx.w - bx.y);

        // ---- inner loop kept bit-identical to the R2 kernel (exact match) ----
        float bi, bu; int bg = 0;
        {
            float4 gt = sgt[0];
            float ih = fminf(bx.z, gt.z) - fmaxf(bx.x, gt.x);
            float iw = fminf(bx.w, gt.w) - fmaxf(bx.y, gt.y);
            bi = fmaxf(ih, 0.f) * fmaxf(iw, 0.f);
            bu = ba + sga[0] - bi;
        }
        #pragma unroll 4
        for (int g = 1; g < GG; g++) {
            float4 gt = sgt[g];
            float ih = fminf(bx.z, gt.z) - fmaxf(bx.x, gt.x);
            float iw = fminf(bx.w, gt.w) - fmaxf(bx.y, gt.y);
            float ia = fmaxf(ih, 0.f) * fmaxf(iw, 0.f);
            float un = ba + sga[g] - ia;
            if (ia * bu > bi * un) { bi = ia; bu = un; bg = g; }
        }
        float iou = __fdividef(bi, bu);
        bool pos = iou > 0.5f;
        bool neg = iou < 0.5f;
        float nv = noise[b * MM + m];
        float c = pos ? (2.0f + nv) : (neg ? nv : -1.0f);
        unsigned hi = fkey(c);
        unsigned long long key =
            ((unsigned long long)hi << 32) |
            (unsigned long long)(0xFFFFFFFFu - (unsigned)m);
        g_p2l[b * MM + m] = (unsigned char)bg;

        int bin = binof(hi);
        if (bin >= 0) {
            int slot = atomicAdd(&g_hist[b * NBINS + bin], 1);
            if (slot < BCAP)
                g_bucket[(size_t)(b * NBINS + bin) * BCAP + slot] = key;
        }
    }
}

// Warp-level bitonic sort of 64 u64 keys, descending. Element e = 2*lane + s.
__device__ __forceinline__ void warp_sort64(unsigned long long& v0,
                                            unsigned long long& v1) {
    const int lane = threadIdx.x & 31;
    #pragma unroll
    for (unsigned k = 2; k <= 64; k <<= 1) {
        #pragma unroll
        for (unsigned j = k >> 1; j >= 1; j >>= 1) {
            bool desc = (((unsigned)(lane << 1)) & k) == 0;
            if (j == 1) {
                unsigned long long hi2 = v0 > v1 ? v0 : v1;
                unsigned long long lo2 = v0 > v1 ? v1 : v0;
                v0 = desc ? hi2 : lo2;
                v1 = desc ? lo2 : hi2;
            } else {
                unsigned lm = j >> 1;
                unsigned long long o0 = __shfl_xor_sync(0xFFFFFFFFu, v0, lm);
                unsigned long long o1 = __shfl_xor_sync(0xFFFFFFFFu, v1, lm);
                bool up = (lane & lm) == 0;
                bool keepmax = (up == desc);
                v0 = keepmax ? (v0 > o0 ? v0 : o0) : (v0 < o0 ? v0 : o0);
                v1 = keepmax ? (v1 > o1 ? v1 : o1) : (v1 < o1 ? v1 : o1);
            }
        }
    }
}

// ---------------------------------------------------------------------------
// K2: counting-sort select. grid = BB blocks x 1024 threads.
// hist -> suffix scan -> thresholds -> per-warp bucket sorts -> emit 512.
// ---------------------------------------------------------------------------
__global__ __launch_bounds__(1024) void k_select_out(
    const float4* __restrict__ boxes,
    const float4* __restrict__ gts,
    const int*    __restrict__ labels,
    float*        __restrict__ out)
{
    __shared__ int h[NBINS];
    __shared__ int suf[NBINS];
    __shared__ unsigned long long buf[896];
    __shared__ int s_tpos, s_tneg;
    const int b = blockIdx.x;
    const int tid = threadIdx.x;
    const int lane = tid & 31;
    const int warp = tid >> 5;

    if (tid < NBINS) {
        int v = g_hist[b * NBINS + tid];
        g_hist[b * NBINS + tid] = 0;       // re-zero for next graph replay
        h[tid] = v;
        suf[tid] = v;
    }
    if (tid == 0) { s_tpos = NBIN_NEG; s_tneg = 0; }
    __syncthreads();

    // Region-masked suffix scan (neg region [0,512), pos region [512,768))
    #pragma unroll
    for (int d = 1; d < NBIN_NEG; d <<= 1) {
        int add = 0;
        if (tid < NBINS) {
            int e = (tid < NBIN_NEG) ? NBIN_NEG : NBINS;
            if (tid + d < e) add = suf[tid + d];
        }
        __syncthreads();
        if (tid < NBINS) suf[tid] += add;
        __syncthreads();
    }

    // Thresholds: highest bin whose suffix covers the quota (warp-leader atomics)
    if (tid < NBINS) {
        bool qual = (tid >= NBIN_NEG) ? (suf[tid] >= MAXFG) : (suf[tid] >= KOUT);
        unsigned mask = __ballot_sync(0xFFFFFFFFu, qual);
        if (qual && (mask >> (lane + 1)) == 0) {   // highest qualifying lane in warp
            if (tid >= NBIN_NEG) atomicMax(&s_tpos, tid);
            else                 atomicMax(&s_tneg, tid);
        }
    }
    __syncthreads();

    const int tpos = s_tpos, tneg = s_tneg;
    const int pc      = suf[NBIN_NEG];   // total pos count (exact)
    const int ppc     = suf[tpos];       // compacted pos count
    const int negtake = suf[tneg];       // compacted neg count
    const int nposb = NBINS - tpos;
    const int nnegb = NBIN_NEG - tneg;

    // Per-warp: sort each taken bucket in registers, scatter to rank offset.
    for (int i = warp; i < nposb + nnegb; i += 32) {
        int bin = (i < nposb) ? (tpos + i) : (tneg + (i - nposb));
        int cnt = h[bin]; if (cnt > BCAP) cnt = BCAP;
        if (cnt == 0) continue;
        int off;
        if (bin >= NBIN_NEG) off = (bin == NBINS - 1) ? 0 : suf[bin + 1];
        else                 off = ppc + ((bin == NBIN_NEG - 1) ? 0 : suf[bin + 1]);
        const unsigned long long* __restrict__ bk =
            g_bucket + (size_t)(b * NBINS + bin) * BCAP;
        unsigned long long v0 = (2 * lane     < cnt) ? bk[2 * lane]     : 0ULL;
        unsigned long long v1 = (2 * lane + 1 < cnt) ? bk[2 * lane + 1] : 0ULL;
        warp_sort64(v0, v1);
        if (2 * lane     < cnt) buf[off + 2 * lane]     = v0;
        if (2 * lane + 1 < cnt) buf[off + 2 * lane + 1] = v1;
    }
    __syncthreads();

    // Emit 512 outputs
    if (tid < KOUT) {
        const int nsel = pc < MAXFG ? pc : MAXFG;
        const int j    = tid;
        bool have = (j < nsel) || (j - nsel < negtake);
        const int src  = (j < nsel) ? j : (ppc + (j - nsel));
        unsigned long long key = have ? buf[src] : 0ULL;
        unsigned hi = (unsigned)(key >> 32);
        unsigned m  = 0xFFFFFFFFu - (unsigned)(key & 0xFFFFFFFFu);
        bool posb  = hi >= 0xC0000000u;
        bool valid = (hi >= 0x80000000u) && (m < MM);

        float4 roi = make_float4(0.f, 0.f, 0.f, 0.f);
        if (valid) roi = (m < NN) ? boxes[b * NN + m] : gts[b * GG + (m - NN)];

        float4 bt = make_float4(0.f, 0.f, 0.f, 0.f);
        int cls = 0, p2l = 0;
        if (posb && m < MM) {
            int g = (int)g_p2l[b * MM + m];
            bt  = gts[b * GG + g];
            cls = labels[b * GG + g];
            p2l = g;
        }

        // out layout (float32): sbox[32,512,4] ++ scls[32,512] ++ rois[32,512,4] ++ sp2l[32,512]
        float4* sbox_o = (float4*)out + b * KOUT + j;
        float*  scls_o = out + BB * KOUT * 4 + b * KOUT + j;
        float4* rois_o = (float4*)(out + BB * KOUT * 4 + BB * KOUT) + b * KOUT + j;
        float*  sp2l_o = out + BB * KOUT * 4 + BB * KOUT + BB * KOUT * 4 + b * KOUT + j;
        *sbox_o = bt;
        *scls_o = (float)cls;
        *rois_o = roi;
        *sp2l_o = (float)p2l;
    }
}

extern "C" void kernel_launch(void* const* d_in, const int* in_sizes, int n_in,
                              void* d_out, int out_size) {
    const float4* boxes  = (const float4*)d_in[0];
    const float4* gts    = (const float4*)d_in[1];
    const int*    labels = (const int*)d_in[2];
    const float*  noise  = (const float*)d_in[3];
    float* out = (float*)d_out;

    k_iou<<<BB * CHUNKS, 128>>>(boxes, gts, noise);
    k_select_out<<<BB, 1024>>>(boxes, gts, labels, out);
}

// round 4
// speedup vs baseline: 4.7320x; 1.2966x over previous
#include <cuda_runtime.h>
#include <cstdint>

// Problem constants
#define BB 32
#define NN 8192
#define GG 128
#define MM 8320            // N + G
#define KOUT 512
#define MAXFG 128

#define NBIN_NEG 512
#define NBIN_POS 256
#define NBINS 768          // neg bins [0,512), pos bins [512,768)
#define BCAP 64            // bucket capacity (expected load ~16)

#define CHUNKS 37          // per-batch chunks in k_iou (32*37 = 1184 = 8*148 blocks)
#define CHUNK 225          // ceil(8320/37)

// Scratch (no allocations allowed). g_hist is zero at load; k_select re-zeroes
// after reading so graph replays are deterministic.
__device__ int g_hist[BB * NBINS];
__device__ unsigned long long g_bucket[BB * NBINS * BCAP];

__device__ __forceinline__ unsigned int fkey(float f) {
    unsigned int u = __float_as_uint(f);
    return (u & 0x80000000u) ? ~u : (u | 0x80000000u);
}

// Monotone fine binning of the key's high word.
__device__ __forceinline__ int binof(unsigned hi) {
    if (hi < 0x80000000u) return -1;
    float c = __uint_as_float(hi ^ 0x80000000u);
    if (hi >= 0xC0000000u) {
        int t = (int)((c - 2.0f) * (float)NBIN_POS);
        return NBIN_NEG + (t > NBIN_POS - 1 ? NBIN_POS - 1 : t);
    }
    int t = (int)(c * (float)NBIN_NEG);
    return t > NBIN_NEG - 1 ? NBIN_NEG - 1 : t;
}

// ---------------------------------------------------------------------------
// K1: classification only. pos <=> exists g with 3*i_area > (b_area+g_area),
// tracked as max_g of fma(3, ia, -(ba+ga)) whose SIGN is exact.
// grid = 1184 blocks x 128 threads.
// ---------------------------------------------------------------------------
__global__ __launch_bounds__(128) void k_iou(
    const float4* __restrict__ boxes,   // [B][N]  (ymin,xmin,ymax,xmax)
    const float4* __restrict__ gts,     // [B][G]
    const float*  __restrict__ noise)   // [B][M]
{
    __shared__ float4 sgt[GG];
    __shared__ float  sga[GG];
    const int b     = blockIdx.x / CHUNKS;
    const int chunk = blockIdx.x % CHUNKS;
    const int tid   = threadIdx.x;

    {
        float4 g = gts[b * GG + tid];
        sgt[tid] = g;
        sga[tid] = (g.z - g.x) * (g.w - g.y);
    }
    __syncthreads();

    const int mstart = chunk * CHUNK;
    const int mend   = (mstart + CHUNK < MM) ? (mstart + CHUNK) : MM;
    for (int m = mstart + tid; m < mend; m += 128) {
        float4 bx = (m < NN) ? boxes[b * NN + m] : gts[b * GG + (m - NN)];
        float ba = (bx.z - bx.x) * (bx.w - bx.y);
        float nb = -ba;
        float nv = noise[b * MM + m];

        float md = -1e30f;
        #pragma unroll 8
        for (int g = 0; g < GG; g++) {
            float4 gt = sgt[g];
            float ih = fminf(bx.z, gt.z) - fmaxf(bx.x, gt.x);
            float iw = fminf(bx.w, gt.w) - fmaxf(bx.y, gt.y);
            float ia = fmaxf(ih, 0.f) * fmaxf(iw, 0.f);
            float t  = nb - sga[g];                  // = -(ba+ga), sign-exact
            float d  = fmaf(3.0f, ia, t);            // >0 <=> iou > 0.5
            md = fmaxf(md, d);
        }
        bool pos = md > 0.0f;
        bool neg = md < 0.0f;
        float c = pos ? (2.0f + nv) : (neg ? nv : -1.0f);
        unsigned hi = fkey(c);
        unsigned long long key =
            ((unsigned long long)hi << 32) |
            (unsigned long long)(0xFFFFFFFFu - (unsigned)m);

        int bin = binof(hi);
        if (bin >= 0) {
            int slot = atomicAdd(&g_hist[b * NBINS + bin], 1);
            if (slot < BCAP)
                g_bucket[(size_t)(b * NBINS + bin) * BCAP + slot] = key;
        }
    }
}

// Warp-level bitonic sort, descending, 32 elems (1 per lane).
__device__ __forceinline__ void warp_sort32(unsigned long long& v) {
    const int lane = threadIdx.x & 31;
    #pragma unroll
    for (unsigned k = 2; k <= 32; k <<= 1) {
        #pragma unroll
        for (unsigned j = k >> 1; j >= 1; j >>= 1) {
            unsigned long long o = __shfl_xor_sync(0xFFFFFFFFu, v, j);
            bool desc = (lane & k) == 0;
            bool up   = (lane & j) == 0;
            bool keepmax = (up == desc);
            v = keepmax ? (v > o ? v : o) : (v < o ? v : o);
        }
    }
}

// Warp-level bitonic sort, descending, 64 elems (2 per lane: e = 2*lane+s).
__device__ __forceinline__ void warp_sort64(unsigned long long& v0,
                                            unsigned long long& v1) {
    const int lane = threadIdx.x & 31;
    #pragma unroll
    for (unsigned k = 2; k <= 64; k <<= 1) {
        #pragma unroll
        for (unsigned j = k >> 1; j >= 1; j >>= 1) {
            bool desc = (((unsigned)(lane << 1)) & k) == 0;
            if (j == 1) {
                unsigned long long hi2 = v0 > v1 ? v0 : v1;
                unsigned long long lo2 = v0 > v1 ? v1 : v0;
                v0 = desc ? hi2 : lo2;
                v1 = desc ? lo2 : hi2;
            } else {
                unsigned lm = j >> 1;
                unsigned long long o0 = __shfl_xor_sync(0xFFFFFFFFu, v0, lm);
                unsigned long long o1 = __shfl_xor_sync(0xFFFFFFFFu, v1, lm);
                bool up = (lane & lm) == 0;
                bool keepmax = (up == desc);
                v0 = keepmax ? (v0 > o0 ? v0 : o0) : (v0 < o0 ? v0 : o0);
                v1 = keepmax ? (v1 > o1 ? v1 : o1) : (v1 < o1 ? v1 : o1);
            }
        }
    }
}

// ---------------------------------------------------------------------------
// K2: counting-sort select + emit (with exact argmax recompute for pos rows).
// grid = BB blocks x 1024 threads.
// ---------------------------------------------------------------------------
__global__ __launch_bounds__(1024) void k_select_out(
    const float4* __restrict__ boxes,
    const float4* __restrict__ gts,
    const int*    __restrict__ labels,
    float*        __restrict__ out)
{
    __shared__ float4 sgt[GG];
    __shared__ float  sga[GG];
    __shared__ int h[NBINS];
    __shared__ int suf[NBINS];
    __shared__ unsigned long long buf[896];
    __shared__ int s_tpos, s_tneg;
    const int b = blockIdx.x;
    const int tid = threadIdx.x;
    const int lane = tid & 31;
    const int warp = tid >> 5;

    if (tid < GG) {
        float4 g = gts[b * GG + tid];
        sgt[tid] = g;
        sga[tid] = (g.z - g.x) * (g.w - g.y);
    }
    if (tid < NBINS) {
        int v = g_hist[b * NBINS + tid];
        g_hist[b * NBINS + tid] = 0;       // re-zero for next graph replay
        h[tid] = v;
        suf[tid] = v;
    }
    if (tid == 0) { s_tpos = NBIN_NEG; s_tneg = 0; }
    __syncthreads();

    // Region-masked suffix scan (neg region [0,512), pos region [512,768))
    #pragma unroll
    for (int d = 1; d < NBIN_NEG; d <<= 1) {
        int add = 0;
        if (tid < NBINS) {
            int e = (tid < NBIN_NEG) ? NBIN_NEG : NBINS;
            if (tid + d < e) add = suf[tid + d];
        }
        __syncthreads();
        if (tid < NBINS) suf[tid] += add;
        __syncthreads();
    }

    // Thresholds: highest bin whose suffix covers the quota
    if (tid < NBINS) {
        bool qual = (tid >= NBIN_NEG) ? (suf[tid] >= MAXFG) : (suf[tid] >= KOUT);
        unsigned mask = __ballot_sync(0xFFFFFFFFu, qual);
        if (qual && (mask >> (lane + 1)) == 0) {
            if (tid >= NBIN_NEG) atomicMax(&s_tpos, tid);
            else                 atomicMax(&s_tneg, tid);
        }
    }
    __syncthreads();

    const int tpos = s_tpos, tneg = s_tneg;
    const int pc      = suf[NBIN_NEG];   // total pos count (exact)
    const int ppc     = suf[tpos];       // compacted pos count
    const int negtake = suf[tneg];       // compacted neg count
    const int nposb = NBINS - tpos;
    const int nnegb = NBIN_NEG - tneg;
    const int nb_tot = nposb + nnegb;

    // Phase A: copy surviving buckets gmem -> smem (loads pipeline across bins)
    for (int i = warp; i < nb_tot; i += 32) {
        int bin = (i < nposb) ? (tpos + i) : (tneg + (i - nposb));
        int cnt = h[bin]; if (cnt > BCAP) cnt = BCAP;
        if (cnt == 0) continue;
        int off;
        if (bin >= NBIN_NEG) off = (bin == NBINS - 1) ? 0 : suf[bin + 1];
        else                 off = ppc + ((bin == NBIN_NEG - 1) ? 0 : suf[bin + 1]);
        const unsigned long long* __restrict__ bk =
            g_bucket + (size_t)(b * NBINS + bin) * BCAP;
        if (lane < cnt)           buf[off + lane]      = bk[lane];
        if (32 + lane < cnt)      buf[off + 32 + lane] = bk[32 + lane];
    }
    __syncthreads();

    // Phase B: per-warp adaptive sort of each bucket region in smem
    for (int i = warp; i < nb_tot; i += 32) {
        int bin = (i < nposb) ? (tpos + i) : (tneg + (i - nposb));
        int cnt = h[bin]; if (cnt > BCAP) cnt = BCAP;
        if (cnt <= 1) continue;
        int off;
        if (bin >= NBIN_NEG) off = (bin == NBINS - 1) ? 0 : suf[bin + 1];
        else                 off = ppc + ((bin == NBIN_NEG - 1) ? 0 : suf[bin + 1]);
        if (cnt <= 32) {
            unsigned long long v = (lane < cnt) ? buf[off + lane] : 0ULL;
            warp_sort32(v);
            if (lane < cnt) buf[off + lane] = v;
        } else {
            unsigned long long v0 = (2 * lane     < cnt) ? buf[off + 2 * lane]     : 0ULL;
            unsigned long long v1 = (2 * lane + 1 < cnt) ? buf[off + 2 * lane + 1] : 0ULL;
            warp_sort64(v0, v1);
            if (2 * lane     < cnt) buf[off + 2 * lane]     = v0;
            if (2 * lane + 1 < cnt) buf[off + 2 * lane + 1] = v1;
        }
    }
    __syncthreads();

    // Emit 512 outputs; pos rows recompute exact argmax (R2-identical loop)
    if (tid < KOUT) {
        const int nsel = pc < MAXFG ? pc : MAXFG;
        const int j    = tid;
        bool have = (j < nsel) || (j - nsel < negtake);
        const int src  = (j < nsel) ? j : (ppc + (j - nsel));
        unsigned long long key = have ? buf[src] : 0ULL;
        unsigned hi = (unsigned)(key >> 32);
        unsigned m  = 0xFFFFFFFFu - (unsigned)(key & 0xFFFFFFFFu);
        bool posb  = hi >= 0xC0000000u;
        bool valid = (hi >= 0x80000000u) && (m < MM);

        float4 roi = make_float4(0.f, 0.f, 0.f, 0.f);
        if (valid) roi = (m < NN) ? boxes[b * NN + m] : gts[b * GG + (m - NN)];

        float4 bt = make_float4(0.f, 0.f, 0.f, 0.f);
        int cls = 0, p2l = 0;
        if (posb && m < MM) {
            float4 bx = roi;
            float ba = (bx.z - bx.x) * (bx.w - bx.y);
            float bi, bu; int bg = 0;
            {
                float4 gt = sgt[0];
                float ih = fminf(bx.z, gt.z) - fmaxf(bx.x, gt.x);
                float iw = fminf(bx.w, gt.w) - fmaxf(bx.y, gt.y);
                bi = fmaxf(ih, 0.f) * fmaxf(iw, 0.f);
                bu = ba + sga[0] - bi;
            }
            #pragma unroll 4
            for (int g = 1; g < GG; g++) {
                float4 gt = sgt[g];
                float ih = fminf(bx.z, gt.z) - fmaxf(bx.x, gt.x);
                float iw = fminf(bx.w, gt.w) - fmaxf(bx.y, gt.y);
                float ia = fmaxf(ih, 0.f) * fmaxf(iw, 0.f);
                float un = ba + sga[g] - ia;
                if (ia * bu > bi * un) { bi = ia; bu = un; bg = g; }
            }
            bt  = sgt[bg];
            cls = labels[b * GG + bg];
            p2l = bg;
        }

        // out layout (float32): sbox[32,512,4] ++ scls[32,512] ++ rois[32,512,4] ++ sp2l[32,512]
        float4* sbox_o = (float4*)out + b * KOUT + j;
        float*  scls_o = out + BB * KOUT * 4 + b * KOUT + j;
        float4* rois_o = (float4*)(out + BB * KOUT * 4 + BB * KOUT) + b * KOUT + j;
        float*  sp2l_o = out + BB * KOUT * 4 + BB * KOUT + BB * KOUT * 4 + b * KOUT + j;
        *sbox_o = bt;
        *scls_o = (float)cls;
        *rois_o = roi;
        *sp2l_o = (float)p2l;
    }
}

extern "C" void kernel_launch(void* const* d_in, const int* in_sizes, int n_in,
                              void* d_out, int out_size) {
    const float4* boxes  = (const float4*)d_in[0];
    const float4* gts    = (const float4*)d_in[1];
    const int*    labels = (const int*)d_in[2];
    const float*  noise  = (const float*)d_in[3];
    float* out = (float*)d_out;

    k_iou<<<BB * CHUNKS, 128>>>(boxes, gts, noise);
    k_select_out<<<BB, 1024>>>(boxes, gts, labels, out);
}

// round 6
// speedup vs baseline: 5.1230x; 1.0826x over previous
#include <cuda_runtime.h>
#include <cstdint>

// Problem constants
#define BB 32
#define NN 8192
#define GG 128
#define MM 8320            // N + G
#define KOUT 512
#define MAXFG 128

#define NBIN_NEG 512
#define NBIN_POS 256
#define NBINS 768          // neg bins [0,512), pos bins [512,768)
#define BCAP 64            // bucket capacity (expected load ~16)

#define CHUNKS 37          // per-batch chunks in k_iou (32*37 = 1184 = 8*148 blocks)
#define CHUNK 225          // ceil(8320/37)

#define SORT_SLICES 8
#define SORT_WARPS 24      // 768 threads
#define SORT_STRIDE (SORT_SLICES * SORT_WARPS)   // 192 warps per batch

typedef unsigned long long u64;

// Scratch (no allocations allowed). g_hist is zero at load; k_emit re-zeroes.
__device__ int g_hist[BB * NBINS];
__device__ u64 g_bucket[BB * NBINS * BCAP];
__device__ u64 g_sorted[BB * 896];
__device__ int g_meta[BB * 4];

__device__ __forceinline__ unsigned int fkey(float f) {
    unsigned int u = __float_as_uint(f);
    return (u & 0x80000000u) ? ~u : (u | 0x80000000u);
}

// Monotone fine binning of the key's high word.
__device__ __forceinline__ int binof(unsigned hi) {
    if (hi < 0x80000000u) return -1;
    float c = __uint_as_float(hi ^ 0x80000000u);
    if (hi >= 0xC0000000u) {
        int t = (int)((c - 2.0f) * (float)NBIN_POS);
        return NBIN_NEG + (t > NBIN_POS - 1 ? NBIN_POS - 1 : t);
    }
    int t = (int)(c * (float)NBIN_NEG);
    return t > NBIN_NEG - 1 ? NBIN_NEG - 1 : t;
}

// ---------------------------------------------------------------------------
// K1: classification only (scalar, R4-identical math).
// pos <=> max_g fma(3, ia, -(ba+ga)) > 0 ; sign is exact under RN rounding.
// grid = 1184 blocks x 128 threads.
// ---------------------------------------------------------------------------
__global__ __launch_bounds__(128) void k_iou(
    const float4* __restrict__ boxes,   // [B][N]  (ymin,xmin,ymax,xmax)
    const float4* __restrict__ gts,     // [B][G]
    const float*  __restrict__ noise)   // [B][M]
{
    __shared__ float4 sgt[GG];
    __shared__ float  sga[GG];
    const int b     = blockIdx.x / CHUNKS;
    const int chunk = blockIdx.x % CHUNKS;
    const int tid   = threadIdx.x;

    {
        float4 g = gts[b * GG + tid];
        sgt[tid] = g;
        sga[tid] = (g.z - g.x) * (g.w - g.y);
    }
    __syncthreads();

    const int mstart = chunk * CHUNK;
    const int mend   = (mstart + CHUNK < MM) ? (mstart + CHUNK) : MM;
    for (int m = mstart + tid; m < mend; m += 128) {
        float4 bx = (m < NN) ? boxes[b * NN + m] : gts[b * GG + (m - NN)];
        float ba = (bx.z - bx.x) * (bx.w - bx.y);
        float nb = -ba;
        float nv = noise[b * MM + m];

        float md = -1e30f;
        #pragma unroll 8
        for (int g = 0; g < GG; g++) {
            float4 gt = sgt[g];
            float ih = fminf(bx.z, gt.z) - fmaxf(bx.x, gt.x);
            float iw = fminf(bx.w, gt.w) - fmaxf(bx.y, gt.y);
            float ia = fmaxf(ih, 0.f) * fmaxf(iw, 0.f);
            float t  = nb - sga[g];                  // = -(ba+ga), sign-exact
            float d  = fmaf(3.0f, ia, t);            // >0 <=> iou > 0.5
            md = fmaxf(md, d);
        }
        bool pos = md > 0.0f;
        bool neg = md < 0.0f;
        float c = pos ? (2.0f + nv) : (neg ? nv : -1.0f);
        unsigned hi = fkey(c);
        u64 key = ((u64)hi << 32) | (u64)(0xFFFFFFFFu - (unsigned)m);

        int bin = binof(hi);
        if (bin >= 0) {
            int slot = atomicAdd(&g_hist[b * NBINS + bin], 1);
            if (slot < BCAP)
                g_bucket[(size_t)(b * NBINS + bin) * BCAP + slot] = key;
        }
    }
}

// Warp-level bitonic sort, descending, 32 elems (1 per lane).
__device__ __forceinline__ void warp_sort32(u64& v) {
    const int lane = threadIdx.x & 31;
    #pragma unroll
    for (unsigned k = 2; k <= 32; k <<= 1) {
        #pragma unroll
        for (unsigned j = k >> 1; j >= 1; j >>= 1) {
            u64 o = __shfl_xor_sync(0xFFFFFFFFu, v, j);
            bool desc = (lane & k) == 0;
            bool up   = (lane & j) == 0;
            bool keepmax = (up == desc);
            v = keepmax ? (v > o ? v : o) : (v < o ? v : o);
        }
    }
}

// Warp-level bitonic sort, descending, 64 elems (2 per lane: e = 2*lane+s).
__device__ __forceinline__ void warp_sort64(u64& v0, u64& v1) {
    const int lane = threadIdx.x & 31;
    #pragma unroll
    for (unsigned k = 2; k <= 64; k <<= 1) {
        #pragma unroll
        for (unsigned j = k >> 1; j >= 1; j >>= 1) {
            bool desc = (((unsigned)(lane << 1)) & k) == 0;
            if (j == 1) {
                u64 hi2 = v0 > v1 ? v0 : v1;
                u64 lo2 = v0 > v1 ? v1 : v0;
                v0 = desc ? hi2 : lo2;
                v1 = desc ? lo2 : hi2;
            } else {
                unsigned lm = j >> 1;
                u64 o0 = __shfl_xor_sync(0xFFFFFFFFu, v0, lm);
                u64 o1 = __shfl_xor_sync(0xFFFFFFFFu, v1, lm);
                bool up = (lane & lm) == 0;
                bool keepmax = (up == desc);
                v0 = keepmax ? (v0 > o0 ? v0 : o0) : (v0 < o0 ? v0 : o0);
                v1 = keepmax ? (v1 > o1 ? v1 : o1) : (v1 < o1 ? v1 : o1);
            }
        }
    }
}

// ---------------------------------------------------------------------------
// K2a: parallel counting-sort. grid (BB, 8) x 768 threads.
// Each slice-block recomputes hist scan + thresholds, sorts its share of bins
// directly gmem->regs->g_sorted. Slice 0 publishes meta.
// ---------------------------------------------------------------------------
__global__ __launch_bounds__(768) void k_sort(void) {
    __shared__ int h[NBINS];
    __shared__ int suf[NBINS];
    __shared__ int s_tpos, s_tneg;
    const int b = blockIdx.x;
    const int slice = blockIdx.y;
    const int tid = threadIdx.x;
    const int lane = tid & 31;
    const int warp = tid >> 5;

    if (tid < NBINS) {
        int v = g_hist[b * NBINS + tid];
        if (v > BCAP) v = BCAP;
        h[tid] = v;
        suf[tid] = v;
    }
    if (tid == 0) { s_tpos = NBIN_NEG; s_tneg = 0; }
    __syncthreads();

    // Region-masked suffix scan (neg [0,512), pos [512,768))
    #pragma unroll
    for (int d = 1; d < NBIN_NEG; d <<= 1) {
        int add = 0;
        if (tid < NBINS) {
            int e = (tid < NBIN_NEG) ? NBIN_NEG : NBINS;
            if (tid + d < e) add = suf[tid + d];
        }
        __syncthreads();
        if (tid < NBINS) suf[tid] += add;
        __syncthreads();
    }

    if (tid < NBINS) {
        bool qual = (tid >= NBIN_NEG) ? (suf[tid] >= MAXFG) : (suf[tid] >= KOUT);
        unsigned mask = __ballot_sync(0xFFFFFFFFu, qual);
        if (qual && (mask >> (lane + 1)) == 0) {
            if (tid >= NBIN_NEG) atomicMax(&s_tpos, tid);
            else                 atomicMax(&s_tneg, tid);
        }
    }
    __syncthreads();

    const int tpos = s_tpos, tneg = s_tneg;
    const int pc      = suf[NBIN_NEG];
    const int ppc     = suf[tpos];
    const int negtake = suf[tneg];
    const int nposb = NBINS - tpos;
    const int nnegb = NBIN_NEG - tneg;
    const int nb_tot = nposb + nnegb;

    if (slice == 0 && tid == 0) {
        g_meta[b * 4 + 0] = pc;
        g_meta[b * 4 + 1] = ppc;
        g_meta[b * 4 + 2] = negtake;
    }

    const int gw = slice * SORT_WARPS + warp;
    for (int i = gw; i < nb_tot; i += SORT_STRIDE) {
        int bin = (i < nposb) ? (tpos + i) : (tneg + (i - nposb));
        int cnt = h[bin];
        if (cnt == 0) continue;
        int off;
        if (bin >= NBIN_NEG) off = (bin == NBINS - 1) ? 0 : suf[bin + 1];
        else                 off = ppc + ((bin == NBIN_NEG - 1) ? 0 : suf[bin + 1]);
        const u64* __restrict__ bk = g_bucket + (size_t)(b * NBINS + bin) * BCAP;
        u64* __restrict__ dst = g_sorted + b * 896 + off;
        if (cnt <= 32) {
            u64 v = (lane < cnt) ? bk[lane] : 0ULL;
            warp_sort32(v);
            if (lane < cnt) dst[lane] = v;
        } else {
            u64 v0 = (2 * lane     < cnt) ? bk[2 * lane]     : 0ULL;
            u64 v1 = (2 * lane + 1 < cnt) ? bk[2 * lane + 1] : 0ULL;
            warp_sort64(v0, v1);
            if (2 * lane     < cnt) dst[2 * lane]     = v0;
            if (2 * lane + 1 < cnt) dst[2 * lane + 1] = v1;
        }
    }
}

// ---------------------------------------------------------------------------
// K2b: emit 512 rows per batch (+ argmax recompute for pos rows), re-zero hist.
// grid = BB x 1024.
// ---------------------------------------------------------------------------
__global__ __launch_bounds__(1024) void k_emit(
    const float4* __restrict__ boxes,
    const float4* __restrict__ gts,
    const int*    __restrict__ labels,
    float*        __restrict__ out)
{
    __shared__ float4 sgt[GG];
    __shared__ float  sga[GG];
    __shared__ int s_meta[3];
    const int b = blockIdx.x;
    const int tid = threadIdx.x;

    if (tid < NBINS) g_hist[b * NBINS + tid] = 0;   // replay determinism
    if (tid < GG) {
        float4 g = gts[b * GG + tid];
        sgt[tid] = g;
        sga[tid] = (g.z - g.x) * (g.w - g.y);
    }
    if (tid < 3) s_meta[tid] = g_meta[b * 4 + tid];
    __syncthreads();

    if (tid < KOUT) {
        const int pc      = s_meta[0];
        const int ppc     = s_meta[1];
        const int negtake = s_meta[2];
        const int nsel = pc < MAXFG ? pc : MAXFG;
        const int j    = tid;
        bool have = (j < nsel) || (j - nsel < negtake);
        const int src  = (j < nsel) ? j : (ppc + (j - nsel));
        u64 key = have ? g_sorted[b * 896 + src] : 0ULL;
        unsigned hi = (unsigned)(key >> 32);
        unsigned m  = 0xFFFFFFFFu - (unsigned)(key & 0xFFFFFFFFu);
        bool posb  = hi >= 0xC0000000u;
        bool valid = (hi >= 0x80000000u) && (m < MM);

        float4 roi = make_float4(0.f, 0.f, 0.f, 0.f);
        if (valid) roi = (m < NN) ? boxes[b * NN + m] : gts[b * GG + (m - NN)];

        float4 bt = make_float4(0.f, 0.f, 0.f, 0.f);
        int cls = 0, p2l = 0;
        if (posb && m < MM) {
            float4 bx = roi;
            float ba = (bx.z - bx.x) * (bx.w - bx.y);
            float bi, bu; int bg = 0;
            {
                float4 gt = sgt[0];
                float ih = fminf(bx.z, gt.z) - fmaxf(bx.x, gt.x);
                float iw = fminf(bx.w, gt.w) - fmaxf(bx.y, gt.y);
                bi = fmaxf(ih, 0.f) * fmaxf(iw, 0.f);
                bu = ba + sga[0] - bi;
            }
            #pragma unroll 4
            for (int g = 1; g < GG; g++) {
                float4 gt = sgt[g];
                float ih = fminf(bx.z, gt.z) - fmaxf(bx.x, gt.x);
                float iw = fminf(bx.w, gt.w) - fmaxf(bx.y, gt.y);
                float ia = fmaxf(ih, 0.f) * fmaxf(iw, 0.f);
                float un = ba + sga[g] - ia;
                if (ia * bu > bi * un) { bi = ia; bu = un; bg = g; }
            }
            bt  = sgt[bg];
            cls = labels[b * GG + bg];
            p2l = bg;
        }

        // out layout: sbox[32,512,4] ++ scls[32,512] ++ rois[32,512,4] ++ sp2l[32,512]
        float4* sbox_o = (float4*)out + b * KOUT + j;
        float*  scls_o = out + BB * KOUT * 4 + b * KOUT + j;
        float4* rois_o = (float4*)(out + BB * KOUT * 4 + BB * KOUT) + b * KOUT + j;
        float*  sp2l_o = out + BB * KOUT * 4 + BB * KOUT + BB * KOUT * 4 + b * KOUT + j;
        *sbox_o = bt;
        *scls_o = (float)cls;
        *rois_o = roi;
        *sp2l_o = (float)p2l;
    }
}

extern "C" void kernel_launch(void* const* d_in, const int* in_sizes, int n_in,
                              void* d_out, int out_size) {
    const float4* boxes  = (const float4*)d_in[0];
    const float4* gts    = (const float4*)d_in[1];
    const int*    labels = (const int*)d_in[2];
    const float*  noise  = (const float*)d_in[3];
    float* out = (float*)d_out;

    k_iou<<<BB * CHUNKS, 128>>>(boxes, gts, noise);
    k_sort<<<dim3(BB, SORT_SLICES), 768>>>();
    k_emit<<<BB, 1024>>>(boxes, gts, labels, out);
}